// round 13
// baseline (speedup 1.0000x reference)
#include <cuda_runtime.h>
#include <cuda_pipeline.h>

#define DIM 1024
#define NROWS 32        // B*T = 2*16 distinct kv rows
#define TPF 1560        // tokens per frame

// Scratch (no cudaMalloc allowed): intermediate v and final per-frame y.
__device__ float g_v[NROWS * DIM];
__device__ float g_y[NROWS * DIM];

#define KCH 256                               // K per pipeline chunk
#define NSTAGE 3
#define STAGE_FLOATS ((8 + 16) * KCH)         // 24KB per stage
#define SMEM_BYTES (NSTAGE * STAGE_FLOATS * 4)  // 72KB ring

// ---- packed fp32x2 helpers (fp32-exact, halves FFMA issue count) ----
__device__ __forceinline__ unsigned long long pk(float lo, float hi) {
    unsigned long long r;
    asm("mov.b64 %0, {%1, %2};" : "=l"(r) : "f"(lo), "f"(hi));
    return r;
}
__device__ __forceinline__ void fma2(unsigned long long& a,
                                     unsigned long long x, unsigned long long w) {
    asm("fma.rn.f32x2 %0, %1, %2, %0;" : "+l"(a) : "l"(x), "l"(w));
}
__device__ __forceinline__ float2 unpk(unsigned long long a) {
    float lo, hi;
    asm("mov.b64 {%0, %1}, %2;" : "=f"(lo), "=f"(hi) : "l"(a));
    return make_float2(lo, hi);
}

// OUT[r, col] = sum_k IN[r, k] * W[col, k] + bias[col]   (proven R9 body)
__global__ __launch_bounds__(256) void gemm32_kernel(
    const float* __restrict__ in,
    const float* __restrict__ W,
    const float* __restrict__ bias,
    float* __restrict__ out,
    const float* __restrict__ pf)     // next-GEMM weights to prefetch (or null)
{
    extern __shared__ float s[];

    const int tid  = threadIdx.x;
    const int lane = tid & 31;
    const int warp = tid >> 5;
    const int rg   = warp & 3;
    const int cg   = warp >> 2;
    const int cb   = blockIdx.x & 127;       // col block (8 cols)
    const int rb   = blockIdx.x >> 7;        // row block (16 rows)
    const int row0 = rb * 16;
    const int col0 = cb * 8;

    const float4* Wg = reinterpret_cast<const float4*>(W + (size_t)col0 * DIM);
    const float4* Xg = reinterpret_cast<const float4*>(in + (size_t)row0 * DIM);

    auto stage_chunk = [&](int ch, int st) {
        float4* sW4 = reinterpret_cast<float4*>(s + st * STAGE_FLOATS);
        float4* sX4 = sW4 + 8 * (KCH / 4);
        const int k4 = ch * (KCH / 4);
        #pragma unroll
        for (int f = tid; f < 8 * 64; f += 256) {
            int c = f >> 6, j = f & 63;
            __pipeline_memcpy_async(&sW4[f], &Wg[(size_t)c * 256 + k4 + j], 16);
        }
        #pragma unroll
        for (int f = tid; f < 16 * 64; f += 256) {
            int r = f >> 6, j = f & 63;
            __pipeline_memcpy_async(&sX4[f], &Xg[(size_t)r * 256 + k4 + j], 16);
        }
        __pipeline_commit();
    };

    stage_chunk(0, 0);
    stage_chunk(1, 1);

    if (pf) {
        const char* base = reinterpret_cast<const char*>(pf) + (size_t)col0 * DIM * 4;
        asm volatile("prefetch.global.L2 [%0];" :: "l"(base + tid * 128));
    }

    unsigned long long acc2[4][4];
    #pragma unroll
    for (int r = 0; r < 4; r++)
        #pragma unroll
        for (int c = 0; c < 4; c++) acc2[r][c] = 0ull;

    #pragma unroll
    for (int ch = 0; ch < 4; ch++) {
        const int st = ch % NSTAGE;
        __pipeline_wait_prior(ch < 3 ? 1 : 0);
        __syncthreads();
        if (ch < 2) stage_chunk(ch + 2, (ch + 2) % NSTAGE);

        const float* sW = s + st * STAGE_FLOATS;          // [8][256]
        const float* sX = sW + 8 * KCH;                   // [16][256]
        #pragma unroll
        for (int half = 0; half < 2; half++) {
            const int k = half * 128 + lane * 4;
            unsigned long long wlo[4], whi[4], xlo[4], xhi[4];
            #pragma unroll
            for (int c = 0; c < 4; c++) {
                float4 w = *reinterpret_cast<const float4*>(&sW[(cg * 4 + c) * KCH + k]);
                wlo[c] = pk(w.x, w.y); whi[c] = pk(w.z, w.w);
            }
            #pragma unroll
            for (int r = 0; r < 4; r++) {
                float4 x = *reinterpret_cast<const float4*>(&sX[(rg * 4 + r) * KCH + k]);
                xlo[r] = pk(x.x, x.y); xhi[r] = pk(x.z, x.w);
            }
            #pragma unroll
            for (int r = 0; r < 4; r++)
                #pragma unroll
                for (int c = 0; c < 4; c++) {
                    fma2(acc2[r][c], xlo[r], wlo[c]);
                    fma2(acc2[r][c], xhi[r], whi[c]);
                }
        }
    }

    float acc[4][4];
    #pragma unroll
    for (int r = 0; r < 4; r++)
        #pragma unroll
        for (int c = 0; c < 4; c++) {
            float2 p = unpk(acc2[r][c]);
            acc[r][c] = p.x + p.y;
        }
    #pragma unroll
    for (int off = 16; off; off >>= 1)
        #pragma unroll
        for (int r = 0; r < 4; r++)
            #pragma unroll
            for (int c = 0; c < 4; c++)
                acc[r][c] += __shfl_xor_sync(0xffffffffu, acc[r][c], off);

    float res = 0.0f;
    #pragma unroll
    for (int r = 0; r < 4; r++)
        #pragma unroll
        for (int c = 0; c < 4; c++)
            if (lane == r * 4 + c) res = acc[r][c];

    if (lane < 16) {
        const int r = lane >> 2, c = lane & 3;
        const int grow = row0 + rg * 4 + r;
        const int gcol = col0 + cg * 4 + c;
        out[grow * DIM + gcol] = res + bias[gcol];
    }
}

// Broadcast via TMA bulk stores: each CTA owns 195 consecutive token-rows
// (all in frame bx/8 since 195*8 == 1560). It replicates the frame's 4KB
// row 24x in smem (96KB), then issues 9 cp.async.bulk stores (8 x 96KB +
// 1 x 12KB) covering its 780KB chunk. The TMA engine streams smem->L2->DRAM
// directly: NO L1tex wavefronts, NO per-128B STG issue -- removing the pipe
// that ncu showed hottest (L1=75%) in the STG version.
#define BCHUNK 24
#define ROWS_PER_CTA 195
#define BSMEM (BCHUNK * 4096)     // 96KB

__global__ __launch_bounds__(256) void bcast_tma_kernel(
    const float4* __restrict__ y4,
    char* __restrict__ out)
{
    extern __shared__ float4 sb[];            // BCHUNK rows x 256 float4
    const int bx  = blockIdx.x;
    const int tid = threadIdx.x;
    const int f   = bx >> 3;                  // frame 0..31

    const float4 val = y4[f * 256 + tid];
    #pragma unroll
    for (int r = 0; r < BCHUNK; r++)
        sb[r * 256 + tid] = val;
    __syncthreads();

    if (tid == 0) {
        asm volatile("fence.proxy.async.shared::cta;" ::: "memory");
        unsigned saddr = (unsigned)__cvta_generic_to_shared(sb);
        char* dst = out + (size_t)bx * ROWS_PER_CTA * 4096;
        #pragma unroll
        for (int i = 0; i < 8; i++) {
            asm volatile(
                "cp.async.bulk.global.shared::cta.bulk_group [%0], [%1], %2;"
                :: "l"(dst + (size_t)i * BSMEM), "r"(saddr), "n"(BSMEM)
                : "memory");
        }
        // tail: 195 - 8*24 = 3 rows
        asm volatile(
            "cp.async.bulk.global.shared::cta.bulk_group [%0], [%1], %2;"
            :: "l"(dst + (size_t)8 * BSMEM), "r"(saddr), "n"(3 * 4096)
            : "memory");
        asm volatile("cp.async.bulk.commit_group;" ::: "memory");
        asm volatile("cp.async.bulk.wait_group 0;" ::: "memory");
    }
}

extern "C" void kernel_launch(void* const* d_in, const int* in_sizes, int n_in,
                              void* d_out, int out_size)
{
    // metadata order: x, c, Wq, bq, Wk, bk, Wv, bv, Wo, bo
    // softmax over a length-1 kv axis is identically 1 -> x/Wq/bq/Wk/bk unused.
    const float* c  = (const float*)d_in[1];
    const float* Wv = (const float*)d_in[6];
    const float* bv = (const float*)d_in[7];
    const float* Wo = (const float*)d_in[8];
    const float* bo = (const float*)d_in[9];
    float* out = (float*)d_out;

    void* vptr = nullptr;
    void* yptr = nullptr;
    cudaGetSymbolAddress(&vptr, g_v);
    cudaGetSymbolAddress(&yptr, g_y);
    float* v = (float*)vptr;
    float* y = (float*)yptr;

    cudaFuncSetAttribute(gemm32_kernel,
                         cudaFuncAttributeMaxDynamicSharedMemorySize, SMEM_BYTES);
    cudaFuncSetAttribute(bcast_tma_kernel,
                         cudaFuncAttributeMaxDynamicSharedMemorySize, BSMEM);

    // v = c @ Wv^T + bv   (prefetch Wo into L2 under this kernel's compute)
    gemm32_kernel<<<256, 256, SMEM_BYTES>>>(c, Wv, bv, v, Wo);
    // y = v @ Wo^T + bo   (Wo now L2-hot)
    gemm32_kernel<<<256, 256, SMEM_BYTES>>>(v, Wo, bo, y, nullptr);
    // out[b, t*1560+i, :] = y[b,t,:]   (204 MB broadcast via TMA bulk stores)
    bcast_tma_kernel<<<256, 256, BSMEM>>>((const float4*)y, (char*)out);

    (void)in_sizes; (void)n_in; (void)out_size;
}

// round 14
// speedup vs baseline: 1.1428x; 1.1428x over previous
#include <cuda_runtime.h>
#include <cuda_pipeline.h>

#define DIM 1024
#define NROWS 32        // B*T = 2*16 distinct kv rows
#define TPF 1560        // tokens per frame

// Scratch (no cudaMalloc allowed): intermediate v and final per-frame y.
__device__ float g_v[NROWS * DIM];
__device__ float g_y[NROWS * DIM];

#define KCH 256                               // K per pipeline chunk
#define NSTAGE 3
#define STAGE_FLOATS ((8 + 16) * KCH)         // 24KB per stage
#define SMEM_BYTES (NSTAGE * STAGE_FLOATS * 4)  // 72KB ring

// ---- packed fp32x2 helpers (fp32-exact, halves FFMA issue count) ----
__device__ __forceinline__ unsigned long long pk(float lo, float hi) {
    unsigned long long r;
    asm("mov.b64 %0, {%1, %2};" : "=l"(r) : "f"(lo), "f"(hi));
    return r;
}
__device__ __forceinline__ void fma2(unsigned long long& a,
                                     unsigned long long x, unsigned long long w) {
    asm("fma.rn.f32x2 %0, %1, %2, %0;" : "+l"(a) : "l"(x), "l"(w));
}
__device__ __forceinline__ float2 unpk(unsigned long long a) {
    float lo, hi;
    asm("mov.b64 {%0, %1}, %2;" : "=f"(lo), "=f"(hi) : "l"(a));
    return make_float2(lo, hi);
}

// OUT[r, col] = sum_k IN[r, k] * W[col, k] + bias[col]   (proven R9 body)
// PDL: triggers its dependent's launch at entry; if sync_dep, the pre-sync
// section only L2-prefetches this kernel's OWN W tile (independent of the
// predecessor's output), then cudaGridDependencySynchronize() before any
// dependent read.
__global__ __launch_bounds__(256) void gemm32_kernel(
    const float* __restrict__ in,
    const float* __restrict__ W,
    const float* __restrict__ bias,
    float* __restrict__ out,
    const float* __restrict__ pf,     // weight tile to L2-prefetch (or null)
    int sync_dep)                     // 1: wait for predecessor before reading `in`
{
    extern __shared__ float s[];

    const int tid  = threadIdx.x;
    const int lane = tid & 31;
    const int warp = tid >> 5;
    const int rg   = warp & 3;
    const int cg   = warp >> 2;
    const int cb   = blockIdx.x & 127;       // col block (8 cols)
    const int rb   = blockIdx.x >> 7;        // row block (16 rows)
    const int row0 = rb * 16;
    const int col0 = cb * 8;

    // Let the dependent kernel begin launching immediately (it still waits
    // for this grid's completion at its own cudaGridDependencySynchronize()).
    cudaTriggerProgrammaticLaunchCompletion();

    // Pre-sync work: L2-prefetch a weight tile (no dependency on predecessor).
    if (pf) {
        const char* base = reinterpret_cast<const char*>(pf) + (size_t)col0 * DIM * 4;
        asm volatile("prefetch.global.L2 [%0];" :: "l"(base + tid * 128));
    }

    if (sync_dep) cudaGridDependencySynchronize();

    const float4* Wg = reinterpret_cast<const float4*>(W + (size_t)col0 * DIM);
    const float4* Xg = reinterpret_cast<const float4*>(in + (size_t)row0 * DIM);

    auto stage_chunk = [&](int ch, int st) {
        float4* sW4 = reinterpret_cast<float4*>(s + st * STAGE_FLOATS);
        float4* sX4 = sW4 + 8 * (KCH / 4);
        const int k4 = ch * (KCH / 4);
        #pragma unroll
        for (int f = tid; f < 8 * 64; f += 256) {
            int c = f >> 6, j = f & 63;
            __pipeline_memcpy_async(&sW4[f], &Wg[(size_t)c * 256 + k4 + j], 16);
        }
        #pragma unroll
        for (int f = tid; f < 16 * 64; f += 256) {
            int r = f >> 6, j = f & 63;
            __pipeline_memcpy_async(&sX4[f], &Xg[(size_t)r * 256 + k4 + j], 16);
        }
        __pipeline_commit();
    };

    stage_chunk(0, 0);
    stage_chunk(1, 1);

    unsigned long long acc2[4][4];
    #pragma unroll
    for (int r = 0; r < 4; r++)
        #pragma unroll
        for (int c = 0; c < 4; c++) acc2[r][c] = 0ull;

    #pragma unroll
    for (int ch = 0; ch < 4; ch++) {
        const int st = ch % NSTAGE;
        __pipeline_wait_prior(ch < 3 ? 1 : 0);
        __syncthreads();
        if (ch < 2) stage_chunk(ch + 2, (ch + 2) % NSTAGE);

        const float* sW = s + st * STAGE_FLOATS;          // [8][256]
        const float* sX = sW + 8 * KCH;                   // [16][256]
        #pragma unroll
        for (int half = 0; half < 2; half++) {
            const int k = half * 128 + lane * 4;
            unsigned long long wlo[4], whi[4], xlo[4], xhi[4];
            #pragma unroll
            for (int c = 0; c < 4; c++) {
                float4 w = *reinterpret_cast<const float4*>(&sW[(cg * 4 + c) * KCH + k]);
                wlo[c] = pk(w.x, w.y); whi[c] = pk(w.z, w.w);
            }
            #pragma unroll
            for (int r = 0; r < 4; r++) {
                float4 x = *reinterpret_cast<const float4*>(&sX[(rg * 4 + r) * KCH + k]);
                xlo[r] = pk(x.x, x.y); xhi[r] = pk(x.z, x.w);
            }
            #pragma unroll
            for (int r = 0; r < 4; r++)
                #pragma unroll
                for (int c = 0; c < 4; c++) {
                    fma2(acc2[r][c], xlo[r], wlo[c]);
                    fma2(acc2[r][c], xhi[r], whi[c]);
                }
        }
    }

    float acc[4][4];
    #pragma unroll
    for (int r = 0; r < 4; r++)
        #pragma unroll
        for (int c = 0; c < 4; c++) {
            float2 p = unpk(acc2[r][c]);
            acc[r][c] = p.x + p.y;
        }
    #pragma unroll
    for (int off = 16; off; off >>= 1)
        #pragma unroll
        for (int r = 0; r < 4; r++)
            #pragma unroll
            for (int c = 0; c < 4; c++)
                acc[r][c] += __shfl_xor_sync(0xffffffffu, acc[r][c], off);

    float res = 0.0f;
    #pragma unroll
    for (int r = 0; r < 4; r++)
        #pragma unroll
        for (int c = 0; c < 4; c++)
            if (lane == r * 4 + c) res = acc[r][c];

    if (lane < 16) {
        const int r = lane >> 2, c = lane & 3;
        const int grow = row0 + rg * 4 + r;
        const int gcol = col0 + cg * 4 + c;
        out[grow * DIM + gcol] = res + bias[gcol];
    }
}

// Broadcast y[frame, :] to all 1560 rows of the frame (best-known version:
// streaming stores, grid (130,32) -- at the chip store cap). PDL-launched:
// its launch/wave-setup overlaps gemm2's tail; data read only after GridSync.
__global__ __launch_bounds__(256) void bcast_kernel(
    const float4* __restrict__ y4,
    float4* __restrict__ out4)
{
    cudaGridDependencySynchronize();

    const int f   = blockIdx.y;                  // frame 0..31
    const int tid = threadIdx.x;
    const float4 val = y4[f * 256 + tid];

    const int per_frame = TPF * 256;             // 399,360 float4 per frame
    const long base = (long)f * per_frame;
    const int stride = gridDim.x * 256;

    for (int i = blockIdx.x * 256 + tid; i < per_frame; i += stride) {
        __stcs(&out4[base + i], val);
    }
}

extern "C" void kernel_launch(void* const* d_in, const int* in_sizes, int n_in,
                              void* d_out, int out_size)
{
    // metadata order: x, c, Wq, bq, Wk, bk, Wv, bv, Wo, bo
    // softmax over a length-1 kv axis is identically 1 -> x/Wq/bq/Wk/bk unused.
    const float* c  = (const float*)d_in[1];
    const float* Wv = (const float*)d_in[6];
    const float* bv = (const float*)d_in[7];
    const float* Wo = (const float*)d_in[8];
    const float* bo = (const float*)d_in[9];
    float* out = (float*)d_out;

    void* vptr = nullptr;
    void* yptr = nullptr;
    cudaGetSymbolAddress(&vptr, g_v);
    cudaGetSymbolAddress(&yptr, g_y);
    float* v = (float*)vptr;
    float* y = (float*)yptr;

    cudaFuncSetAttribute(gemm32_kernel,
                         cudaFuncAttributeMaxDynamicSharedMemorySize, SMEM_BYTES);

    // gemm1: plain launch (no predecessor in this replay).
    {
        void* args[] = {(void*)&c, (void*)&Wv, (void*)&bv, (void*)&v,
                        (void*)&Wo, /*sync_dep=*/nullptr};
        int zero = 0; args[5] = &zero;
        cudaLaunchKernel((const void*)gemm32_kernel, dim3(256), dim3(256),
                         args, SMEM_BYTES, 0);
    }

    // gemm2 + bcast: PDL so each launches during its predecessor's execution.
    cudaLaunchAttribute attr;
    attr.id = cudaLaunchAttributeProgrammaticStreamSerialization;
    attr.val.programmaticStreamSerializationAllowed = 1;

    {
        cudaLaunchConfig_t cfg = {};
        cfg.gridDim = dim3(256); cfg.blockDim = dim3(256);
        cfg.dynamicSmemBytes = SMEM_BYTES; cfg.stream = 0;
        cfg.attrs = &attr; cfg.numAttrs = 1;
        const float* in2 = v; const float* pf2 = Wo; int sd = 1;
        cudaError_t e = cudaLaunchKernelEx(&cfg, gemm32_kernel,
                                           in2, Wo, bo, y, pf2, sd);
        if (e != cudaSuccess) {   // fallback: plain launch (still correct)
            gemm32_kernel<<<256, 256, SMEM_BYTES>>>(v, Wo, bo, y, Wo, 1);
        }
    }
    {
        cudaLaunchConfig_t cfg = {};
        cfg.gridDim = dim3(130, 32); cfg.blockDim = dim3(256);
        cfg.dynamicSmemBytes = 0; cfg.stream = 0;
        cfg.attrs = &attr; cfg.numAttrs = 1;
        const float4* y4 = (const float4*)y; float4* o4 = (float4*)out;
        cudaError_t e = cudaLaunchKernelEx(&cfg, bcast_kernel, y4, o4);
        if (e != cudaSuccess) {
            bcast_kernel<<<dim3(130, 32), 256>>>((const float4*)y, (float4*)out);
        }
    }

    (void)in_sizes; (void)n_in; (void)out_size;
}